// round 13
// baseline (speedup 1.0000x reference)
#include <cuda_runtime.h>
#include <cuda_bf16.h>
#include <cstdint>
#include <math.h>

#define B_ 16
#define T_ 2048
#define C_ 1024
#define H_ 64
#define ROWS_ (B_ * T_)   // 32768

// Scratch
__device__ float g_q[ROWS_ * H_];
__device__ float g_k[ROWS_ * H_];
__device__ float g_v[ROWS_ * H_];
__device__ __align__(16) __nv_bfloat16 g_xhi[ROWS_ * C_];   // 64 MB
__device__ __align__(16) __nv_bfloat16 g_xlo[ROWS_ * C_];   // 64 MB
__device__ __align__(16) __nv_bfloat16 g_wT_hi[3 * 64 * 1024];
__device__ __align__(16) __nv_bfloat16 g_wT_lo[3 * 64 * 1024];

// log2(e) / sqrt(H) folded into q so attention uses exp2f directly
#define QSCALE 0.18033688011112042f

__device__ __forceinline__ uint32_t smem_u32(const void* p) {
    uint32_t a;
    asm("{ .reg .u64 t; cvta.to.shared.u64 t, %1; cvt.u32.u64 %0, t; }"
        : "=r"(a) : "l"(p));
    return a;
}
__device__ __forceinline__ void cp16(uint32_t dst, const void* src) {
    asm volatile("cp.async.ca.shared.global [%0], [%1], 16;"
                 :: "r"(dst), "l"(src) : "memory");
}
#define CP_COMMIT() asm volatile("cp.async.commit_group;" ::: "memory")
#define CP_WAIT0()  asm volatile("cp.async.wait_group 0;" ::: "memory")

__device__ __forceinline__ uint32_t pack_bf16x2(float a, float b) {
    __nv_bfloat162 t = __floats2bfloat162_rn(a, b);
    return *(uint32_t*)&t;
}
// mma.sync m16n8k16 bf16 (compiles for compute_103; runs on tensor pipe)
__device__ __forceinline__ void mma_bf16(float* d, const uint32_t* a,
                                         uint32_t b0, uint32_t b1) {
    asm volatile(
        "mma.sync.aligned.m16n8k16.row.col.f32.bf16.bf16.f32 "
        "{%0,%1,%2,%3}, {%4,%5,%6,%7}, {%8,%9}, {%0,%1,%2,%3};"
        : "+f"(d[0]), "+f"(d[1]), "+f"(d[2]), "+f"(d[3])
        : "r"(a[0]), "r"(a[1]), "r"(a[2]), "r"(a[3]), "r"(b0), "r"(b1));
}

// ---------------------------------------------------------------------------
// Kernel 0a: weights -> transposed bf16 hi/lo.  grid 192, block 256.
// ---------------------------------------------------------------------------
__global__ void convert_w_kernel(const float* __restrict__ wq,
                                 const float* __restrict__ wk,
                                 const float* __restrict__ wv)
{
    const int w = blockIdx.x >> 6;
    const int n = blockIdx.x & 63;
    const float* __restrict__ src = (w == 0) ? wq : (w == 1) ? wk : wv;
    const int base = w * 65536 + n * 1024;
#pragma unroll
    for (int i = 0; i < 4; i++) {
        int k = threadIdx.x + i * 256;
        float v = src[(size_t)k * 64 + n];
        __nv_bfloat16 h = __float2bfloat16(v);
        g_wT_hi[base + k] = h;
        g_wT_lo[base + k] = __float2bfloat16(v - __bfloat162float(h));
    }
}

// ---------------------------------------------------------------------------
// Kernel 0b: X -> bf16 hi/lo (linear layout).  grid 8192, block 256.
// ---------------------------------------------------------------------------
__global__ void convert_x_kernel(const float* __restrict__ x)
{
    int f0 = blockIdx.x * 1024 + threadIdx.x;
#pragma unroll
    for (int it = 0; it < 4; it++) {
        int f = f0 + it * 256;
        float4 v = ((const float4*)x)[f];
        __nv_bfloat16 hx = __float2bfloat16(v.x);
        __nv_bfloat16 hy = __float2bfloat16(v.y);
        __nv_bfloat16 hz = __float2bfloat16(v.z);
        __nv_bfloat16 hw = __float2bfloat16(v.w);
        uint2 hp, lp;
        __nv_bfloat162 h01 = __nv_bfloat162(hx, hy), h23 = __nv_bfloat162(hz, hw);
        hp.x = *(uint32_t*)&h01; hp.y = *(uint32_t*)&h23;
        lp.x = pack_bf16x2(v.x - __bfloat162float(hx), v.y - __bfloat162float(hy));
        lp.y = pack_bf16x2(v.z - __bfloat162float(hz), v.w - __bfloat162float(hw));
        *(uint2*)&g_xhi[(size_t)f * 4] = hp;
        *(uint2*)&g_xlo[(size_t)f * 4] = lp;
    }
}

// ---------------------------------------------------------------------------
// Kernel 1: QKV projection, pipelined 3-term bf16 HMMA.
// grid (256, 3): CTA = 128 rows x one weight (N=64).  256 threads = 8 warps,
// warp grid 4(M:32) x 2(N:32).  K: 16 chunks of 64, cp.async double-buffered.
// Stage (48KB): AHI 16K | ALO 16K | BHI 8K | BLO 8K.  Two stages = 96KB.
// ---------------------------------------------------------------------------
#define STAGE_SZ 49152
#define PROJ_SMEM 98304

__global__ __launch_bounds__(256, 2)
void qkv_proj_mma()
{
    extern __shared__ char sm[];
    const uint32_t smBase = smem_u32(sm);

    const int tid = threadIdx.x;
    const int wid = tid >> 5;
    const int lane = tid & 31;
    const int g  = lane >> 2;
    const int tg = lane & 3;
    const int m0 = (wid >> 1) * 32;
    const int n0 = (wid & 1) * 32;
    const int mBase = blockIdx.x * 128;
    const int w = blockIdx.y;

    float acc[2][4][4];
#pragma unroll
    for (int mt = 0; mt < 2; mt++)
#pragma unroll
        for (int nt = 0; nt < 4; nt++)
#pragma unroll
            for (int e = 0; e < 4; e++) acc[mt][nt][e] = 0.0f;

    // ---- staging lambda-equivalent (macro-expanded by hand) ----
    // A: 2048 cp16 (hi+lo), B: 1024 cp16 (hi+lo) across 256 threads.
#define STAGE_CHUNK(kc, buf)                                                   \
    do {                                                                       \
        const uint32_t base = smBase + (buf) * STAGE_SZ;                       \
        _Pragma("unroll")                                                      \
        for (int it = 0; it < 4; it++) {                                       \
            int idx = tid + it * 256;                                          \
            int r = idx >> 3, k8 = idx & 7;                                    \
            uint32_t off = (uint32_t)(r * 128) +                               \
                           (((uint32_t)(k8 * 16)) ^ ((uint32_t)((r & 7) << 4)));\
            size_t src = (size_t)(mBase + r) * C_ + (kc) * 64 + k8 * 8;        \
            cp16(base + off, &g_xhi[src]);                                     \
            cp16(base + 16384 + off, &g_xlo[src]);                             \
        }                                                                      \
        _Pragma("unroll")                                                      \
        for (int it = 0; it < 2; it++) {                                       \
            int idx = tid + it * 256;                                          \
            int n = idx >> 3, k8 = idx & 7;                                    \
            uint32_t off = (uint32_t)(n * 128) +                               \
                           (((uint32_t)(k8 * 16)) ^ ((uint32_t)((n & 7) << 4)));\
            size_t src = (size_t)w * 65536 + (size_t)n * 1024 + (kc) * 64 + k8 * 8;\
            cp16(base + 32768 + off, &g_wT_hi[src]);                           \
            cp16(base + 40960 + off, &g_wT_lo[src]);                           \
        }                                                                      \
        CP_COMMIT();                                                           \
    } while (0)

    STAGE_CHUNK(0, 0);

    for (int kc = 0; kc < 16; kc++) {
        CP_WAIT0();
        __syncthreads();
        if (kc < 15) STAGE_CHUNK(kc + 1, (kc + 1) & 1);

        const char* Abase = sm + (kc & 1) * STAGE_SZ;
        const char* Bbase = Abase + 32768;

#pragma unroll
        for (int ks = 0; ks < 4; ks++) {
            const uint32_t c2 = (uint32_t)(ks * 32 + tg * 4);
            uint32_t Ah[2][4], Al[2][4];
#pragma unroll
            for (int mt = 0; mt < 2; mt++) {
                int r0 = m0 + mt * 16 + g;
                uint32_t swz = (uint32_t)((r0 & 7) << 4);
                uint32_t row0 = (uint32_t)(r0 * 128);
                uint32_t cA = c2 ^ swz, cB = (c2 + 16) ^ swz;
                Ah[mt][0] = *(const uint32_t*)(Abase + row0 + cA);
                Ah[mt][1] = *(const uint32_t*)(Abase + row0 + 1024 + cA);
                Ah[mt][2] = *(const uint32_t*)(Abase + row0 + cB);
                Ah[mt][3] = *(const uint32_t*)(Abase + row0 + 1024 + cB);
                Al[mt][0] = *(const uint32_t*)(Abase + 16384 + row0 + cA);
                Al[mt][1] = *(const uint32_t*)(Abase + 16384 + row0 + 1024 + cA);
                Al[mt][2] = *(const uint32_t*)(Abase + 16384 + row0 + cB);
                Al[mt][3] = *(const uint32_t*)(Abase + 16384 + row0 + 1024 + cB);
            }
#pragma unroll
            for (int nt = 0; nt < 4; nt++) {
                int n = n0 + nt * 8 + g;
                uint32_t swz = (uint32_t)((n & 7) << 4);
                uint32_t brow = (uint32_t)(n * 128);
                uint32_t cA = c2 ^ swz, cB = (c2 + 16) ^ swz;
                uint32_t bh0 = *(const uint32_t*)(Bbase + brow + cA);
                uint32_t bh1 = *(const uint32_t*)(Bbase + brow + cB);
                uint32_t bl0 = *(const uint32_t*)(Bbase + 8192 + brow + cA);
                uint32_t bl1 = *(const uint32_t*)(Bbase + 8192 + brow + cB);
#pragma unroll
                for (int mt = 0; mt < 2; mt++) {
                    mma_bf16(acc[mt][nt], Ah[mt], bh0, bh1);
                    mma_bf16(acc[mt][nt], Ah[mt], bl0, bl1);
                    mma_bf16(acc[mt][nt], Al[mt], bh0, bh1);
                }
            }
        }
        // no trailing sync: next iteration's wait+sync protects buffer reuse
    }

    // ---- epilogue ----
    float* __restrict__ dst = (w == 0) ? g_q : (w == 1) ? g_k : g_v;
    const float s = (w == 0) ? QSCALE : 1.0f;
#pragma unroll
    for (int mt = 0; mt < 2; mt++) {
#pragma unroll
        for (int nt = 0; nt < 4; nt++) {
            int row = mBase + m0 + mt * 16 + g;
            int col = n0 + nt * 8 + 2 * tg;
            float2 v0 = { acc[mt][nt][0] * s, acc[mt][nt][1] * s };
            float2 v1 = { acc[mt][nt][2] * s, acc[mt][nt][3] * s };
            *(float2*)&dst[(size_t)row * H_ + col] = v0;
            *(float2*)&dst[(size_t)(row + 8) * H_ + col] = v1;
        }
    }
}

// ---------------------------------------------------------------------------
// Kernel 2: causal flash attention (round-10 version, 219.6us — unchanged)
// ---------------------------------------------------------------------------
#define ATTN_SMEM 81920   // Q 16K | K0 16K | K1 16K | V0 16K | V1 16K

__global__ __launch_bounds__(128, 2)
void attn_kernel(float* __restrict__ out)
{
    extern __shared__ char sm[];
    float* Qs = (float*)sm;
    const uint32_t smBase = smem_u32(sm);

    const int tid = threadIdx.x;
    const int j = tid & 15;
    const int i = tid >> 4;

    const int b  = blockIdx.x & 15;
    const int qt = 31 - (blockIdx.x >> 4);
    const size_t bRow = (size_t)b * T_;
    const int qBase = qt * 64;

#pragma unroll
    for (int it = 0; it < 8; it++) {
        int f4 = tid + it * 128;
        int r = f4 >> 4, c = f4 & 15;
        *(float4*)&Qs[r * 64 + c * 4] =
            *(const float4*)&g_q[(bRow + qBase + r) * H_ + c * 4];
    }

    {
        const uint32_t kB = smBase + 16384;
        const uint32_t vB = smBase + 49152;
#pragma unroll
        for (int it = 0; it < 8; it++) {
            int f4 = tid + it * 128;
            int r = f4 >> 4, c = f4 & 15;
            cp16(kB + 4 * (r * 64 + 4 * (c ^ (r >> 2))),
                 &g_k[(bRow + r) * H_ + c * 4]);
            cp16(vB + 4 * (r * 64 + 4 * c),
                 &g_v[(bRow + r) * H_ + c * 4]);
        }
        CP_COMMIT();
    }

    float m_i[8], l_i[8], acc[8][4];
#pragma unroll
    for (int m = 0; m < 8; m++) {
        m_i[m] = -1e30f; l_i[m] = 0.0f;
#pragma unroll
        for (int n = 0; n < 4; n++) acc[m][n] = 0.0f;
    }

    for (int kt = 0; kt <= qt; kt++) {
        const int cur = kt & 1;
        float* Ks = (float*)(sm + 16384 + cur * 16384);
        float* Vs = (float*)(sm + 49152 + cur * 16384);
        float* Ps = Ks;

        CP_WAIT0();
        __syncthreads();

        if (kt < qt) {
            const int nxtBase = (kt + 1) * 64;
            const uint32_t kB = smBase + 16384 + (cur ^ 1) * 16384;
            const uint32_t vB = smBase + 49152 + (cur ^ 1) * 16384;
#pragma unroll
            for (int it = 0; it < 8; it++) {
                int f4 = tid + it * 128;
                int r = f4 >> 4, c = f4 & 15;
                cp16(kB + 4 * (r * 64 + 4 * (c ^ (r >> 2))),
                     &g_k[(bRow + nxtBase + r) * H_ + c * 4]);
                cp16(vB + 4 * (r * 64 + 4 * c),
                     &g_v[(bRow + nxtBase + r) * H_ + c * 4]);
            }
            CP_COMMIT();
        }

        float S[8][4];
#pragma unroll
        for (int m = 0; m < 8; m++)
#pragma unroll
            for (int n = 0; n < 4; n++) S[m][n] = 0.0f;

#pragma unroll 4
        for (int h4 = 0; h4 < 16; h4++) {
            float4 kf[4];
#pragma unroll
            for (int n = 0; n < 4; n++)
                kf[n] = *(const float4*)&Ks[(4 * j + n) * 64 + 4 * (h4 ^ j)];
#pragma unroll
            for (int m = 0; m < 8; m++) {
                float4 a = *(const float4*)&Qs[(8 * i + m) * 64 + 4 * h4];
#pragma unroll
                for (int n = 0; n < 4; n++) {
                    S[m][n] += a.x * kf[n].x;
                    S[m][n] += a.y * kf[n].y;
                    S[m][n] += a.z * kf[n].z;
                    S[m][n] += a.w * kf[n].w;
                }
            }
        }
        __syncthreads();

        if (kt == qt) {
#pragma unroll
            for (int m = 0; m < 8; m++)
#pragma unroll
                for (int n = 0; n < 4; n++)
                    if (4 * j + n > 8 * i + m) S[m][n] = -1e30f;
        }

#pragma unroll
        for (int m = 0; m < 8; m++) {
            float rmax = fmaxf(fmaxf(S[m][0], S[m][1]), fmaxf(S[m][2], S[m][3]));
#pragma unroll
            for (int msk = 8; msk >= 1; msk >>= 1)
                rmax = fmaxf(rmax, __shfl_xor_sync(0xffffffffu, rmax, msk));
            float mNew = fmaxf(m_i[m], rmax);
            float factor = exp2f(m_i[m] - mNew);
            float4 pv;
            pv.x = exp2f(S[m][0] - mNew);
            pv.y = exp2f(S[m][1] - mNew);
            pv.z = exp2f(S[m][2] - mNew);
            pv.w = exp2f(S[m][3] - mNew);
            float rsum = pv.x + pv.y + pv.z + pv.w;
#pragma unroll
            for (int msk = 8; msk >= 1; msk >>= 1)
                rsum += __shfl_xor_sync(0xffffffffu, rsum, msk);
            l_i[m] = l_i[m] * factor + rsum;
            m_i[m] = mNew;
            acc[m][0] *= factor; acc[m][1] *= factor;
            acc[m][2] *= factor; acc[m][3] *= factor;
            *(float4*)&Ps[(8 * i + m) * 64 + 4 * j] = pv;
        }
        __syncthreads();

#pragma unroll 4
        for (int kv4 = 0; kv4 < 16; kv4++) {
            float4 vf[4];
#pragma unroll
            for (int n = 0; n < 4; n++)
                vf[n] = *(const float4*)&Vs[(4 * kv4 + n) * 64 + 4 * j];
#pragma unroll
            for (int m = 0; m < 8; m++) {
                float4 pm = *(const float4*)&Ps[(8 * i + m) * 64 + 4 * kv4];
                acc[m][0] += pm.x * vf[0].x; acc[m][0] += pm.y * vf[1].x;
                acc[m][0] += pm.z * vf[2].x; acc[m][0] += pm.w * vf[3].x;
                acc[m][1] += pm.x * vf[0].y; acc[m][1] += pm.y * vf[1].y;
                acc[m][1] += pm.z * vf[2].y; acc[m][1] += pm.w * vf[3].y;
                acc[m][2] += pm.x * vf[0].z; acc[m][2] += pm.y * vf[1].z;
                acc[m][2] += pm.z * vf[2].z; acc[m][2] += pm.w * vf[3].z;
                acc[m][3] += pm.x * vf[0].w; acc[m][3] += pm.y * vf[1].w;
                acc[m][3] += pm.z * vf[2].w; acc[m][3] += pm.w * vf[3].w;
            }
        }
    }

#pragma unroll
    for (int m = 0; m < 8; m++) {
        float inv = 1.0f / l_i[m];
        float4 o;
        o.x = acc[m][0] * inv; o.y = acc[m][1] * inv;
        o.z = acc[m][2] * inv; o.w = acc[m][3] * inv;
        *(float4*)&out[(bRow + qBase + 8 * i + m) * H_ + 4 * j] = o;
    }
}

// ---------------------------------------------------------------------------
extern "C" void kernel_launch(void* const* d_in, const int* in_sizes, int n_in,
                              void* d_out, int out_size)
{
    const float* x  = (const float*)d_in[0];
    const float* wq = (const float*)d_in[1];
    const float* wk = (const float*)d_in[2];
    const float* wv = (const float*)d_in[3];
    float* out = (float*)d_out;

    cudaFuncSetAttribute(qkv_proj_mma,
                         cudaFuncAttributeMaxDynamicSharedMemorySize, PROJ_SMEM);
    cudaFuncSetAttribute(attn_kernel,
                         cudaFuncAttributeMaxDynamicSharedMemorySize, ATTN_SMEM);

    convert_w_kernel<<<192, 256>>>(wq, wk, wv);
    convert_x_kernel<<<8192, 256>>>(x);
    dim3 gProj(ROWS_ / 128, 3);
    qkv_proj_mma<<<gProj, 256, PROJ_SMEM>>>();
    attn_kernel<<<16 * 32, 128, ATTN_SMEM>>>(out);
}